// round 2
// baseline (speedup 1.0000x reference)
#include <cuda_runtime.h>
#include <cstdint>

// Problem constants (fixed shapes from reference)
#define DIM      64
#define KCODES   8192
#define NPTS     32768
#define TN       64          // points per block
#define TK       256         // codes per K-chunk
#define CS_LD    260         // padded shared stride for transposed codebook
#define NCHUNK   (KCODES / TK)
#define THREADS  128

// ||c_k||^2 computed with reference-matching rounding (sequential, no FMA)
__device__ float d_cn[KCODES];

__device__ __forceinline__ void fma2(unsigned long long& d,
                                     unsigned long long a,
                                     unsigned long long b) {
    asm("fma.rn.f32x2 %0, %1, %2, %3;" : "=l"(d) : "l"(a), "l"(b), "l"(d));
}
__device__ __forceinline__ unsigned long long pack2(float x) {
    unsigned long long r;
    asm("mov.b64 %0, {%1, %1};" : "=l"(r) : "f"(x));
    return r;
}
__device__ __forceinline__ void unpack2(unsigned long long v, float& lo, float& hi) {
    asm("mov.b64 {%0, %1}, %2;" : "=f"(lo), "=f"(hi) : "l"(v));
}

// nc_k = sum_{d} fl(c_d * c_d), strictly sequential adds (XLA-CPU scalar reduce order)
__global__ void __launch_bounds__(256) norm_kernel(const float* __restrict__ cb) {
    int k = blockIdx.x * 256 + threadIdx.x;
    const float* row = cb + (size_t)k * DIM;
    float s = 0.f;
#pragma unroll
    for (int i = 0; i < DIM; i++) {
        s = __fadd_rn(s, __fmul_rn(row[i], row[i]));
    }
    d_cn[k] = s;
}

// Fused: m = x.c (sequential FMA over d), d2 = fl(fl(nx - 2m) + nc) emulating
// the reference's fp32 expression tree; running argmin; gather+write.
__global__ void __launch_bounds__(THREADS) vq_kernel(const float* __restrict__ ze,
                                                     const float* __restrict__ cb,
                                                     float* __restrict__ out) {
    extern __shared__ float smem[];
    float* xs  = smem;                      // [64 d][64 n]        16384 B
    float* cs  = smem + DIM * TN;           // [64 d][CS_LD k]     66560 B
    float* cn  = cs + DIM * CS_LD;          // [256]                1024 B
    float* nxs = cn + TK;                   // [64]                  256 B
    float* rb  = nxs + TN;                  // [64 n][16 kt]        4096 B
    int*   ri  = (int*)(rb + TN * 16);      // [64 n][16 kt]        4096 B
    int*   bx  = ri + TN * 16;              // [64]                  256 B

    const int tid = threadIdx.x;
    const int nt  = tid & 7;    // 8 point-groups of 8 points
    const int kt  = tid >> 3;   // 16 code-groups of 16 codes
    const int n0  = blockIdx.x * TN;
    const int b   = n0 >> 12;        // 4096 = H*W points per batch image
    const int hw0 = n0 & 4095;
    const float* zb = ze + (size_t)b * DIM * 4096 + hw0;

    // Load x tile: xs[d][nl], coalesced along nl (w-dim contiguous).
#pragma unroll
    for (int it = 0; it < (DIM * TN) / THREADS; it++) {
        int e = tid + it * THREADS;
        int nl = e & 63;
        int d  = e >> 6;
        xs[d * 64 + nl] = zb[(size_t)d * 4096 + nl];
    }
    __syncthreads();

    // nx per point: sequential sum of fl(x_d^2), d = 0..63, no FMA contraction.
    if (tid < TN) {
        float s = 0.f;
#pragma unroll
        for (int d = 0; d < DIM; d++) {
            float v = xs[d * 64 + tid];
            s = __fadd_rn(s, __fmul_rn(v, v));
        }
        nxs[tid] = s;
    }
    __syncthreads();

    // This thread's 8 points' nx values
    float nxr[8];
#pragma unroll
    for (int i = 0; i < 8; i++) nxr[i] = nxs[8 * nt + i];

    float best[8];   // running min d2
    int   bi[8];
#pragma unroll
    for (int i = 0; i < 8; i++) { best[i] = 3.4e38f; bi[i] = 0; }

#pragma unroll 1
    for (int ch = 0; ch < NCHUNK; ch++) {
        const int k0 = ch * TK;
        __syncthreads();   // protect cs/cn from previous chunk's readers

        // Load + transpose codebook chunk into cs[d][k] (padded stride).
#pragma unroll
        for (int it = 0; it < (TK * DIM / 4) / THREADS; it++) {
            int e = tid + it * THREADS;   // 0..4095
            int r = e >> 4;               // code row 0..255
            int q = e & 15;               // float4 col
            float4 v = *reinterpret_cast<const float4*>(cb + (size_t)(k0 + r) * DIM + q * 4);
            cs[(4 * q + 0) * CS_LD + r] = v.x;
            cs[(4 * q + 1) * CS_LD + r] = v.y;
            cs[(4 * q + 2) * CS_LD + r] = v.z;
            cs[(4 * q + 3) * CS_LD + r] = v.w;
        }
        cn[tid]       = d_cn[k0 + tid];
        cn[tid + 128] = d_cn[k0 + tid + 128];
        __syncthreads();

        unsigned long long acc[8][8];   // 8 points x 8 code-pairs
#pragma unroll
        for (int i = 0; i < 8; i++)
#pragma unroll
            for (int j = 0; j < 8; j++) acc[i][j] = 0ULL;

        // m = sum_d x_d * c_d, sequential FMA in ascending d (Eigen gebp order)
#pragma unroll 2
        for (int d = 0; d < DIM; d++) {
            float4 xv0 = *reinterpret_cast<const float4*>(&xs[d * 64 + 8 * nt]);
            float4 xv1 = *reinterpret_cast<const float4*>(&xs[d * 64 + 8 * nt + 4]);
            unsigned long long xp[8];
            xp[0] = pack2(xv0.x); xp[1] = pack2(xv0.y);
            xp[2] = pack2(xv0.z); xp[3] = pack2(xv0.w);
            xp[4] = pack2(xv1.x); xp[5] = pack2(xv1.y);
            xp[6] = pack2(xv1.z); xp[7] = pack2(xv1.w);
            const ulonglong2* crow =
                reinterpret_cast<const ulonglong2*>(&cs[d * CS_LD + 16 * kt]);
            ulonglong2 c01 = crow[0];
            ulonglong2 c23 = crow[1];
            ulonglong2 c45 = crow[2];
            ulonglong2 c67 = crow[3];
            unsigned long long cp[8] = {c01.x, c01.y, c23.x, c23.y,
                                        c45.x, c45.y, c67.x, c67.y};
#pragma unroll
            for (int i = 0; i < 8; i++)
#pragma unroll
                for (int j = 0; j < 8; j++)
                    fma2(acc[i][j], xp[i], cp[j]);
        }

        // Fold: d2 = fl(fl(nx - fl(2m)) + nc), ascending k, strict < (first-index ties)
#pragma unroll
        for (int j = 0; j < 8; j++) {
            int kk = 16 * kt + 2 * j;
            float c0 = cn[kk];
            float c1 = cn[kk + 1];
            int kg = k0 + kk;
#pragma unroll
            for (int i = 0; i < 8; i++) {
                float lo, hi;
                unpack2(acc[i][j], lo, hi);
                float t0 = __fadd_rn(nxr[i], -__fmul_rn(2.0f, lo));
                float t1 = __fadd_rn(nxr[i], -__fmul_rn(2.0f, hi));
                float d0 = __fadd_rn(t0, c0);
                float d1 = __fadd_rn(t1, c1);
                if (d0 < best[i]) { best[i] = d0; bi[i] = kg; }
                if (d1 < best[i]) { best[i] = d1; bi[i] = kg + 1; }
            }
        }
    }

    __syncthreads();
    // Cross-thread (kt) reduction per point, lowest-index tie-break
#pragma unroll
    for (int i = 0; i < 8; i++) {
        int p = 8 * nt + i;
        rb[p * 16 + kt] = best[i];
        ri[p * 16 + kt] = bi[i];
    }
    __syncthreads();
    if (tid < TN) {
        float bv = 3.4e38f;
        int   bj = 0x7fffffff;
#pragma unroll
        for (int t = 0; t < 16; t++) {
            float v  = rb[tid * 16 + t];
            int   ix = ri[tid * 16 + t];
            if (v < bv || (v == bv && ix < bj)) { bv = v; bj = ix; }
        }
        bx[tid] = bj;
    }
    __syncthreads();

    // Gather codebook rows; writes coalesced along nl
    float* ob = out + (size_t)b * DIM * 4096 + hw0;
#pragma unroll
    for (int it = 0; it < (DIM * TN) / THREADS; it++) {
        int e = tid + it * THREADS;
        int nl = e & 63;
        int d  = e >> 6;
        ob[(size_t)d * 4096 + nl] = cb[(size_t)bx[nl] * DIM + d];
    }
}

extern "C" void kernel_launch(void* const* d_in, const int* in_sizes, int n_in,
                              void* d_out, int out_size) {
    const float* ze = (const float*)d_in[0];   // [8,64,64,64] f32
    const float* cb = (const float*)d_in[1];   // [8192,64] f32
    float* out = (float*)d_out;                // [8,64,64,64] f32

    const int smem_bytes = (DIM * TN + DIM * CS_LD + TK + TN + TN * 16) * 4 +
                           TN * 16 * 4 + TN * 4;   // 92928 B

    cudaFuncSetAttribute(vq_kernel, cudaFuncAttributeMaxDynamicSharedMemorySize,
                         smem_bytes);

    norm_kernel<<<KCODES / 256, 256>>>(cb);
    vq_kernel<<<NPTS / TN, THREADS, smem_bytes>>>(ze, cb, out);
}

// round 3
// speedup vs baseline: 1.1270x; 1.1270x over previous
#include <cuda_runtime.h>
#include <cstdint>

// Problem constants (fixed shapes from reference)
#define DIM      64
#define KCODES   8192
#define NPTS     32768
#define TN       64          // points per block
#define TK       256         // codes per K-chunk
#define NCHUNK   (KCODES / TK)
#define THREADS  128

// Pre-transposed + chunk-interleaved codebook: row d, windows of 256 codes,
// within a window the 64 float4-chunks are stored at phys(c) = (c&3)*16 + (c>>2).
__device__ float d_cbT[DIM * KCODES];          // 2 MB
// ||c_k||^2 with reference rounding (sequential mul-then-add, no FMA)
__device__ float d_cn[KCODES];

__device__ __forceinline__ void fma2(unsigned long long& d,
                                     unsigned long long a,
                                     unsigned long long b) {
    asm("fma.rn.f32x2 %0, %1, %2, %3;" : "=l"(d) : "l"(a), "l"(b), "l"(d));
}
__device__ __forceinline__ void unpack2(unsigned long long v, float& lo, float& hi) {
    asm("mov.b64 {%0, %1}, %2;" : "=f"(lo), "=f"(hi) : "l"(v));
}

// ---------------------------------------------------------------------------
// prep: transpose codebook into d_cbT (interleaved layout) + compute d_cn.
// One block per 64 codes. Tiny (2 MB moved once).
// ---------------------------------------------------------------------------
__global__ void __launch_bounds__(256) prep_kernel(const float* __restrict__ cb) {
    __shared__ float ts[DIM][65];   // [d][code], padded
    const int tid = threadIdx.x;
    const int k0  = blockIdx.x * 64;

    // Load 64 codes x 64 dims, transpose into ts
#pragma unroll
    for (int i = 0; i < 4; i++) {
        int e = tid + 256 * i;        // 0..1023 float4 units
        int r = e >> 4;               // code 0..63
        int q = e & 15;               // float4 col
        float4 v = *reinterpret_cast<const float4*>(cb + (size_t)(k0 + r) * DIM + 4 * q);
        ts[4 * q + 0][r] = v.x;
        ts[4 * q + 1][r] = v.y;
        ts[4 * q + 2][r] = v.z;
        ts[4 * q + 3][r] = v.w;
    }
    __syncthreads();

    // nc_k = sum_d fl(c_d*c_d), strictly sequential (matches reference rounding)
    if (tid < 64) {
        float s = 0.f;
#pragma unroll
        for (int d = 0; d < DIM; d++)
            s = __fadd_rn(s, __fmul_rn(ts[d][tid], ts[d][tid]));
        d_cn[k0 + tid] = s;
    }

    // Write interleaved-transposed rows
    const int w   = k0 >> 8;              // 256-code window
    const int cb0 = (k0 & 255) >> 2;      // base local chunk (multiple of 16)
#pragma unroll
    for (int i = 0; i < 4; i++) {
        int idx = tid + 256 * i;          // 0..1023 float4 units
        int d   = idx & 63;
        int cc  = idx >> 6;               // 0..15 local chunk within this block
        float4 v = make_float4(ts[d][4 * cc + 0], ts[d][4 * cc + 1],
                               ts[d][4 * cc + 2], ts[d][4 * cc + 3]);
        int c = cb0 + cc;                 // window-local chunk 0..63
        int p = ((c & 3) << 4) | (c >> 2);
        *reinterpret_cast<float4*>(d_cbT + (size_t)d * KCODES + w * 256 + p * 4) = v;
    }
}

// ---------------------------------------------------------------------------
// vq: fused GEMM(f32x2) + exact reference-rounded epilogue + argmin + gather.
// ---------------------------------------------------------------------------
__global__ void __launch_bounds__(THREADS) vq_kernel(const float* __restrict__ ze,
                                                     const float* __restrict__ cb,
                                                     float* __restrict__ out) {
    extern __shared__ float smem[];
    float* xs2 = smem;                      // [64 d][128] packed-dup x    32768 B
    float* cs  = xs2 + DIM * 128;           // [64 d][256] interleaved     65536 B
    float* cn  = cs + DIM * TK;             // [256]                        1024 B
    float* nxs = cn + TK;                   // [64]                          256 B
    float* rb  = nxs + TN;                  // [64 n][16 kt]                4096 B
    int*   ri  = (int*)(rb + TN * 16);      // [64 n][16 kt]                4096 B
    int*   bx  = ri + TN * 16;              // [64]                          256 B

    const int tid = threadIdx.x;
    const int nt  = tid & 7;    // 8 point-groups of 8 points
    const int kt  = tid >> 3;   // 16 code-groups of 16 codes
    const int n0  = blockIdx.x * TN;
    const int b   = n0 >> 12;        // 4096 = H*W points per batch image
    const int hw0 = n0 & 4095;
    const float* zb = ze + (size_t)b * DIM * 4096 + hw0;

    // Fill xs2: each point duplicated into both lanes of an f32 pair,
    // chunk-interleaved: 16B chunk c (= n>>1) stored at (c&3)*8 + (c>>2).
#pragma unroll
    for (int it = 0; it < 32; it++) {
        int e  = tid + it * THREADS;   // 0..4095
        int nl = e & 63;
        int d  = e >> 6;
        float v = zb[(size_t)d * 4096 + nl];
        int c  = nl >> 1;
        int px = ((c & 3) << 3) | (c >> 2);
        float* p = xs2 + d * 128 + px * 4 + (nl & 1) * 2;
        p[0] = v;
        p[1] = v;
    }
    __syncthreads();

    // nx per point: sequential sum of fl(x_d^2), no FMA contraction.
    if (tid < TN) {
        int c  = tid >> 1;
        int px = ((c & 3) << 3) | (c >> 2);
        const float* p = xs2 + px * 4 + (tid & 1) * 2;
        float s = 0.f;
#pragma unroll
        for (int d = 0; d < DIM; d++) {
            float v = p[d * 128];
            s = __fadd_rn(s, __fmul_rn(v, v));
        }
        nxs[tid] = s;
    }
    __syncthreads();

    float nxr[8];
#pragma unroll
    for (int i = 0; i < 8; i++) nxr[i] = nxs[8 * nt + i];

    float best[8];   // running min d2
    int   bi[8];
#pragma unroll
    for (int i = 0; i < 8; i++) { best[i] = 3.4e38f; bi[i] = 0; }

    const ulonglong2* xbase = reinterpret_cast<const ulonglong2*>(xs2) + nt;
    const ulonglong2* cbase = reinterpret_cast<const ulonglong2*>(cs) + kt;

#pragma unroll 1
    for (int ch = 0; ch < NCHUNK; ch++) {
        const int k0 = ch * TK;
        __syncthreads();   // protect cs/cn from previous chunk's readers

        // Chunk fill: straight coalesced copy (layout already interleaved).
        const float4* src = reinterpret_cast<const float4*>(d_cbT) + ch * 64;
        float4* dst = reinterpret_cast<float4*>(cs);
#pragma unroll
        for (int it = 0; it < 32; it++) {
            int e = tid + it * THREADS;   // 0..4095 float4 units
            int d = e >> 6;
            int f = e & 63;
            dst[e] = src[(size_t)d * (KCODES / 4) + f];
        }
        cn[tid]       = d_cn[k0 + tid];
        cn[tid + 128] = d_cn[k0 + tid + 128];
        __syncthreads();

        unsigned long long acc[8][8];   // 8 points x 8 code-pairs (f32x2)
#pragma unroll
        for (int i = 0; i < 8; i++)
#pragma unroll
            for (int j = 0; j < 8; j++) acc[i][j] = 0ULL;

        // m = sum_d x_d * c_d, sequential FMA in ascending d
#pragma unroll 2
        for (int d = 0; d < DIM; d++) {
            ulonglong2 xv0 = xbase[d * 32 + 0];
            ulonglong2 xv1 = xbase[d * 32 + 8];
            ulonglong2 xv2 = xbase[d * 32 + 16];
            ulonglong2 xv3 = xbase[d * 32 + 24];
            ulonglong2 cv0 = cbase[d * 64 + 0];
            ulonglong2 cv1 = cbase[d * 64 + 16];
            ulonglong2 cv2 = cbase[d * 64 + 32];
            ulonglong2 cv3 = cbase[d * 64 + 48];
            unsigned long long xq[8] = {xv0.x, xv0.y, xv1.x, xv1.y,
                                        xv2.x, xv2.y, xv3.x, xv3.y};
            unsigned long long cq[8] = {cv0.x, cv0.y, cv1.x, cv1.y,
                                        cv2.x, cv2.y, cv3.x, cv3.y};
#pragma unroll
            for (int i = 0; i < 8; i++)
#pragma unroll
                for (int j = 0; j < 8; j++)
                    fma2(acc[i][j], xq[i], cq[j]);
        }

        // Fold: d2 = fl(fl(nx - fl(2m)) + nc), ascending k, strict < (first-index ties)
#pragma unroll
        for (int j = 0; j < 8; j++) {
            int kk = 16 * kt + 2 * j;
            float c0 = cn[kk];
            float c1 = cn[kk + 1];
            int kg = k0 + kk;
#pragma unroll
            for (int i = 0; i < 8; i++) {
                float lo, hi;
                unpack2(acc[i][j], lo, hi);
                float t0 = __fadd_rn(nxr[i], -__fmul_rn(2.0f, lo));
                float t1 = __fadd_rn(nxr[i], -__fmul_rn(2.0f, hi));
                float d0 = __fadd_rn(t0, c0);
                float d1 = __fadd_rn(t1, c1);
                if (d0 < best[i]) { best[i] = d0; bi[i] = kg; }
                if (d1 < best[i]) { best[i] = d1; bi[i] = kg + 1; }
            }
        }
    }

    __syncthreads();
    // Cross-thread (kt) reduction per point, lowest-index tie-break
#pragma unroll
    for (int i = 0; i < 8; i++) {
        int p = 8 * nt + i;
        rb[p * 16 + kt] = best[i];
        ri[p * 16 + kt] = bi[i];
    }
    __syncthreads();
    if (tid < TN) {
        float bv = 3.4e38f;
        int   bj = 0x7fffffff;
#pragma unroll
        for (int t = 0; t < 16; t++) {
            float v  = rb[tid * 16 + t];
            int   ix = ri[tid * 16 + t];
            if (v < bv || (v == bv && ix < bj)) { bv = v; bj = ix; }
        }
        bx[tid] = bj;
    }
    __syncthreads();

    // Gather codebook rows; writes coalesced along nl
    float* ob = out + (size_t)b * DIM * 4096 + hw0;
#pragma unroll
    for (int it = 0; it < (DIM * TN) / THREADS; it++) {
        int e = tid + it * THREADS;
        int nl = e & 63;
        int d  = e >> 6;
        ob[(size_t)d * 4096 + nl] = cb[(size_t)bx[nl] * DIM + d];
    }
}

extern "C" void kernel_launch(void* const* d_in, const int* in_sizes, int n_in,
                              void* d_out, int out_size) {
    const float* ze = (const float*)d_in[0];   // [8,64,64,64] f32
    const float* cb = (const float*)d_in[1];   // [8192,64] f32
    float* out = (float*)d_out;                // [8,64,64,64] f32

    const int smem_bytes = (DIM * 128 + DIM * TK + TK + TN + TN * 16) * 4 +
                           TN * 16 * 4 + TN * 4;   // 108032 B

    cudaFuncSetAttribute(vq_kernel, cudaFuncAttributeMaxDynamicSharedMemorySize,
                         smem_bytes);

    prep_kernel<<<KCODES / 64, 256>>>(cb);
    vq_kernel<<<NPTS / TN, THREADS, smem_bytes>>>(ze, cb, out);
}